// round 5
// baseline (speedup 1.0000x reference)
#include <cuda_runtime.h>
#include <cstdint>

// Problem constants
#define BSZ     8
#define KDIM    4096
#define NDIM    11008
#define RPW     8                        // rows per warp task
#define SPLITK  4
#define KCH     (KDIM / SPLITK)          // 1024 floats per K-chunk
#define STAGE_FLOATS 256                 // floats per row per stage
#define STAGE_ROW_BYTES (STAGE_FLOATS * 4)        // 1024
#define STAGE_BYTES (RPW * STAGE_ROW_BYTES)       // 8192
#define NSTAGES (KCH / STAGE_FLOATS)     // 4 stages per task
#define DEPTH   2                        // ring depth per warp
#define WARPS_PER_CTA 8
#define THREADS (WARPS_PER_CTA * 32)     // 256
#define NCTAS   148
#define CTAS_PER_KC (NCTAS / SPLITK)     // 37
#define NROWGROUPS (NDIM / RPW)          // 1376

// smem layout
#define XS_BYTES   (BSZ * KCH * 4)                       // 32768
#define RING_BYTES (DEPTH * STAGE_BYTES)                 // 16384 per warp
#define SMEM_X     0
#define SMEM_RING  XS_BYTES                              // + wid*RING_BYTES
#define SMEM_MBAR  (XS_BYTES + WARPS_PER_CTA * RING_BYTES)   // 163840, + wid*16 + slot*8
#define SMEM_BYTES (SMEM_MBAR + WARPS_PER_CTA * DEPTH * 8)   // 163968

// ---- packed f32x2 FMA ----
__device__ __forceinline__ void ffma2(unsigned long long& d,
                                      unsigned long long a,
                                      unsigned long long b) {
    asm("fma.rn.f32x2 %0, %1, %2, %0;" : "+l"(d) : "l"(a), "l"(b));
}
__device__ __forceinline__ float sum2(unsigned long long a) {
    float lo, hi;
    asm("mov.b64 {%0, %1}, %2;" : "=f"(lo), "=f"(hi) : "l"(a));
    return lo + hi;
}
__device__ __forceinline__ uint32_t smem_u32(const void* p) {
    uint32_t a;
    asm("{ .reg .u64 t; cvta.to.shared.u64 t, %1; cvt.u32.u64 %0, t; }"
        : "=r"(a) : "l"(p));
    return a;
}
__device__ __forceinline__ void lds_v2u64(uint32_t addr,
                                          unsigned long long& a,
                                          unsigned long long& b) {
    asm volatile("ld.shared.v2.u64 {%0, %1}, [%2];" : "=l"(a), "=l"(b) : "r"(addr));
}
__device__ __forceinline__ void mbar_init(uint32_t mbar) {
    asm volatile("mbarrier.init.shared.b64 [%0], 1;" :: "r"(mbar) : "memory");
}
__device__ __forceinline__ void mbar_wait(uint32_t mbar, uint32_t parity) {
    asm volatile(
        "{\n\t"
        ".reg .pred P;\n\t"
        "WAIT_%=:\n\t"
        "mbarrier.try_wait.parity.acquire.cta.shared::cta.b64 P, [%0], %1, 0x989680;\n\t"
        "@P bra.uni DONE_%=;\n\t"
        "bra.uni WAIT_%=;\n\t"
        "DONE_%=:\n\t"
        "}"
        :: "r"(mbar), "r"(parity) : "memory");
}
// issue one stage: 8 rows x 1KB bulk copies + expect_tx
__device__ __forceinline__ void issue_stage(uint32_t dst, const char* src,
                                            uint32_t mbar) {
    asm volatile("mbarrier.arrive.expect_tx.shared.b64 _, [%0], %1;"
                 :: "r"(mbar), "r"((uint32_t)STAGE_BYTES) : "memory");
    #pragma unroll
    for (int r = 0; r < RPW; r++) {
        asm volatile(
            "cp.async.bulk.shared::cta.global.mbarrier::complete_tx::bytes "
            "[%0], [%1], %2, [%3];"
            :: "r"(dst + r * STAGE_ROW_BYTES),
               "l"(src + (size_t)r * KDIM * 4),
               "r"((uint32_t)STAGE_ROW_BYTES),
               "r"(mbar)
            : "memory");
    }
}

extern __shared__ char smem_raw[];

__global__ __launch_bounds__(THREADS, 1)
void asl_gemv_kernel(const float* __restrict__ x,
                     const float* __restrict__ w,
                     float* __restrict__ out) {
    const int tid  = threadIdx.x;
    const int lane = tid & 31;
    const int wid  = tid >> 5;
    const int kc        = blockIdx.x & 3;       // fixed K-chunk per CTA
    const int cta_in_kc = blockIdx.x >> 2;      // 0..36
    const int kbase     = kc * KCH;

    const uint32_t smem_base = smem_u32(smem_raw);
    const uint32_t ring  = smem_base + SMEM_RING + wid * RING_BYTES;
    const uint32_t mbars = smem_base + SMEM_MBAR + wid * (DEPTH * 8);
    const uint32_t xsmem = smem_base;            // x at offset 0

    // init this warp's mbarriers (before syncthreads)
    if (lane == 0) {
        mbar_init(mbars);
        mbar_init(mbars + 8);
    }

    // ---- stage this CTA's x chunk (8 x 1024 floats = 32 KB) ----
    {
        float4* xs4 = reinterpret_cast<float4*>(smem_raw);
        #pragma unroll 4
        for (int i = tid; i < BSZ * KCH / 4; i += THREADS) {
            const int b = i >> 8;                 // / (KCH/4)
            const int o = i & 255;
            xs4[i] = reinterpret_cast<const float4*>(
                x + (size_t)b * KDIM + kbase)[o];
        }
    }
    __syncthreads();

    unsigned seq = 0;   // global stage sequence for this warp (slot/parity)

    for (int rg = cta_in_kc + CTAS_PER_KC * wid; rg < NROWGROUPS;
         rg += CTAS_PER_KC * WARPS_PER_CTA) {
        const int n0 = rg * RPW;
        const char* wr = reinterpret_cast<const char*>(
            w + (size_t)n0 * KDIM + kbase);

        // prologue: fill the depth-2 ring (stages 0 and 1)
        if (lane == 0) {
            issue_stage(ring + ((seq    ) & 1) * STAGE_BYTES,
                        wr,                       mbars + ((seq    ) & 1) * 8);
            issue_stage(ring + ((seq + 1) & 1) * STAGE_BYTES,
                        wr + STAGE_ROW_BYTES,     mbars + ((seq + 1) & 1) * 8);
        }

        unsigned long long acc[RPW][BSZ];
        #pragma unroll
        for (int r = 0; r < RPW; r++)
            #pragma unroll
            for (int b = 0; b < BSZ; b++)
                acc[r][b] = 0ULL;

        #pragma unroll
        for (int it = 0; it < NSTAGES; it++) {
            const int slot = seq & 1;
            mbar_wait(mbars + slot * 8, (seq >> 1) & 1);

            const uint32_t wsl = ring + slot * STAGE_BYTES;
            // two half-chunks of 128 floats per row per stage
            #pragma unroll
            for (int sub = 0; sub < 2; sub++) {
                unsigned long long wv[RPW][2];
                #pragma unroll
                for (int r = 0; r < RPW; r++)
                    lds_v2u64(wsl + r * STAGE_ROW_BYTES + sub * 512 + lane * 16,
                              wv[r][0], wv[r][1]);
                const uint32_t xoff = xsmem +
                    (it * STAGE_FLOATS + sub * 128 + lane * 4) * 4;
                #pragma unroll
                for (int b = 0; b < BSZ; b++) {
                    unsigned long long x0, x1;
                    lds_v2u64(xoff + b * (KCH * 4), x0, x1);
                    #pragma unroll
                    for (int r = 0; r < RPW; r++) {
                        ffma2(acc[r][b], wv[r][0], x0);
                        ffma2(acc[r][b], wv[r][1], x1);
                    }
                }
            }

            // issue stage it+2 into the buffer we just finished
            if (lane == 0 && it + 2 < NSTAGES)
                issue_stage(ring + slot * STAGE_BYTES,
                            wr + (size_t)(it + 2) * STAGE_ROW_BYTES,
                            mbars + slot * 8);
            seq++;
        }

        // ---- warp reduction + split-K atomic accumulation ----
        #pragma unroll
        for (int r = 0; r < RPW; r++) {
            #pragma unroll
            for (int b = 0; b < BSZ; b++) {
                float s = sum2(acc[r][b]);
                s += __shfl_down_sync(0xFFFFFFFFu, s, 16);
                s += __shfl_down_sync(0xFFFFFFFFu, s, 8);
                s += __shfl_down_sync(0xFFFFFFFFu, s, 4);
                s += __shfl_down_sync(0xFFFFFFFFu, s, 2);
                s += __shfl_down_sync(0xFFFFFFFFu, s, 1);
                if (lane == 0)
                    atomicAdd(out + (size_t)b * NDIM + n0 + r, s);
            }
        }
    }
}

// zero-init the output (poisoned to 0xAA by harness)
__global__ void asl_zero_kernel(float* __restrict__ out) {
    const int i = blockIdx.x * blockDim.x + threadIdx.x;   // float4 index
    const int total4 = BSZ * NDIM / 4;                     // 22016
    if (i < total4)
        reinterpret_cast<float4*>(out)[i] = make_float4(0.f, 0.f, 0.f, 0.f);
}

extern "C" void kernel_launch(void* const* d_in, const int* in_sizes, int n_in,
                              void* d_out, int out_size) {
    const float* x = (const float*)d_in[0];
    const float* w = (const float*)d_in[1];
    if (n_in >= 2 && in_sizes[0] == NDIM * KDIM) {   // defensive order fix
        const float* t = x; x = w; w = t;
    }
    float* out = (float*)d_out;

    cudaFuncSetAttribute(asl_gemv_kernel,
                         cudaFuncAttributeMaxDynamicSharedMemorySize,
                         SMEM_BYTES);

    const int total4 = BSZ * NDIM / 4;
    asl_zero_kernel<<<(total4 + 511) / 512, 512>>>(out);
    asl_gemv_kernel<<<NCTAS, THREADS, SMEM_BYTES>>>(x, w, out);
}

// round 6
// speedup vs baseline: 1.2686x; 1.2686x over previous
#include <cuda_runtime.h>
#include <cstdint>

// Problem constants
#define BSZ     8
#define KDIM    4096
#define NDIM    11008
#define RPW     4                        // rows per warp task
#define SPLITK  4
#define KCH     (KDIM / SPLITK)          // 1024 floats per K-chunk
#define KITERS  (KCH / 128)              // 8 iterations (128 floats/row/iter)
#define WARPS_PER_CTA 16
#define THREADS (WARPS_PER_CTA * 32)     // 512
#define CTAS_PER_KC 37
#define NCTAS   (CTAS_PER_KC * SPLITK)   // 148
#define WARPS_PER_KC (CTAS_PER_KC * WARPS_PER_CTA)   // 592
#define NROWGROUPS (NDIM / RPW)          // 2752
#define SMEM_BYTES (BSZ * KCH * 4)       // 32768

// ---- packed f32x2 FMA (Blackwell f32x2 pipe) ----
__device__ __forceinline__ void ffma2(unsigned long long& d,
                                      unsigned long long a,
                                      unsigned long long b) {
    asm("fma.rn.f32x2 %0, %1, %2, %0;" : "+l"(d) : "l"(a), "l"(b));
}
__device__ __forceinline__ float sum2(unsigned long long a) {
    float lo, hi;
    asm("mov.b64 {%0, %1}, %2;" : "=f"(lo), "=f"(hi) : "l"(a));
    return lo + hi;
}
// streaming 128-bit global load as two packed f32x2 words (bypass L1 reuse)
__device__ __forceinline__ void ldg_cs_v2u64(const void* p,
                                             unsigned long long& a,
                                             unsigned long long& b) {
    asm("ld.global.cs.v2.u64 {%0, %1}, [%2];"
        : "=l"(a), "=l"(b) : "l"(p));
}

extern __shared__ float xs[];   // [BSZ][KCH] staged activations for this kc

__global__ __launch_bounds__(THREADS, 1)
void asl_gemv_kernel(const float* __restrict__ x,
                     const float* __restrict__ w,
                     float* __restrict__ out) {
    const int kc        = blockIdx.x & 3;        // fixed K-chunk per CTA
    const int cta_in_kc = blockIdx.x >> 2;       // 0..36
    const int kbase     = kc * KCH;

    // ---- stage this kc's x chunk (8 x 1024 floats = 32 KB) ----
    {
        float4* xs4 = reinterpret_cast<float4*>(xs);
        #pragma unroll 4
        for (int i = threadIdx.x; i < BSZ * KCH / 4; i += THREADS) {
            const int b = i >> 8;                // / (KCH/4)
            const int o = i & 255;
            xs4[i] = reinterpret_cast<const float4*>(
                x + (size_t)b * KDIM + kbase)[o];
        }
    }
    __syncthreads();

    const int lane  = threadIdx.x & 31;
    const int wid   = threadIdx.x >> 5;
    const ulonglong2* xs2 = reinterpret_cast<const ulonglong2*>(xs);

    for (int rg = cta_in_kc * WARPS_PER_CTA + wid; rg < NROWGROUPS;
         rg += WARPS_PER_KC) {
        const int n0 = rg * RPW;
        const char* wr = reinterpret_cast<const char*>(
            w + (size_t)n0 * KDIM + kbase);

        unsigned long long acc[RPW][BSZ];
        #pragma unroll
        for (int r = 0; r < RPW; r++)
            #pragma unroll
            for (int b = 0; b < BSZ; b++)
                acc[r][b] = 0ULL;

        #pragma unroll 2
        for (int it = 0; it < KITERS; it++) {
            const int koff = (it * 32 + lane) * 16;   // byte offset in chunk

            unsigned long long w0l, w0h, w1l, w1h, w2l, w2h, w3l, w3h;
            ldg_cs_v2u64(wr +                 koff, w0l, w0h);
            ldg_cs_v2u64(wr +     KDIM * 4 +  koff, w1l, w1h);
            ldg_cs_v2u64(wr + 2 * KDIM * 4 +  koff, w2l, w2h);
            ldg_cs_v2u64(wr + 3 * KDIM * 4 +  koff, w3l, w3h);

            const int xoff = it * 32 + lane;          // 16B-unit offset
            #pragma unroll
            for (int b = 0; b < BSZ; b++) {
                ulonglong2 xv = xs2[b * (KCH / 4) + xoff];
                ffma2(acc[0][b], w0l, xv.x); ffma2(acc[0][b], w0h, xv.y);
                ffma2(acc[1][b], w1l, xv.x); ffma2(acc[1][b], w1h, xv.y);
                ffma2(acc[2][b], w2l, xv.x); ffma2(acc[2][b], w2h, xv.y);
                ffma2(acc[3][b], w3l, xv.x); ffma2(acc[3][b], w3h, xv.y);
            }
        }

        // ---- epilogue: 3-step shfl, lanes 0-3 hold disjoint partials,
        //      all four RED.ADD (L2 serializes 4 same-address adds ~3cyc) ----
        #pragma unroll
        for (int r = 0; r < RPW; r++) {
            #pragma unroll
            for (int b = 0; b < BSZ; b++) {
                float s = sum2(acc[r][b]);
                s += __shfl_down_sync(0xFFFFFFFFu, s, 16);
                s += __shfl_down_sync(0xFFFFFFFFu, s, 8);
                s += __shfl_down_sync(0xFFFFFFFFu, s, 4);
                if (lane < 4)
                    atomicAdd(out + (size_t)b * NDIM + n0 + r, s);
            }
        }
    }
}

// zero-init the output (poisoned to 0xAA by harness)
__global__ void asl_zero_kernel(float* __restrict__ out) {
    const int i = blockIdx.x * blockDim.x + threadIdx.x;   // float4 index
    const int total4 = BSZ * NDIM / 4;                     // 22016
    if (i < total4)
        reinterpret_cast<float4*>(out)[i] = make_float4(0.f, 0.f, 0.f, 0.f);
}

extern "C" void kernel_launch(void* const* d_in, const int* in_sizes, int n_in,
                              void* d_out, int out_size) {
    const float* x = (const float*)d_in[0];
    const float* w = (const float*)d_in[1];
    if (n_in >= 2 && in_sizes[0] == NDIM * KDIM) {   // defensive order fix
        const float* t = x; x = w; w = t;
    }
    float* out = (float*)d_out;

    cudaFuncSetAttribute(asl_gemv_kernel,
                         cudaFuncAttributeMaxDynamicSharedMemorySize,
                         SMEM_BYTES);

    const int total4 = BSZ * NDIM / 4;
    asl_zero_kernel<<<(total4 + 511) / 512, 512>>>(out);
    asl_gemv_kernel<<<NCTAS, THREADS, SMEM_BYTES>>>(x, w, out);
}

// round 7
// speedup vs baseline: 1.3712x; 1.0809x over previous
#include <cuda_runtime.h>
#include <cstdint>

// Problem constants
#define BSZ     8
#define KDIM    4096
#define NDIM    11008
#define RPW     8                        // rows per task
#define BPT     4                        // batches per task (batch split in 2)
#define SPLITK  4
#define KCH     (KDIM / SPLITK)          // 1024 floats per K-chunk
#define KITERS  (KCH / 128)              // 8 iterations (128 floats/row/iter)
#define WARPS_PER_CTA 16
#define THREADS (WARPS_PER_CTA * 32)     // 512
#define NCTAS   148
#define TOTAL_WARPS (NCTAS * WARPS_PER_CTA)   // 2368
#define NROWGROUPS (NDIM / RPW)          // 1376
#define NTASKS  (NROWGROUPS * SPLITK * 2)     // 11008
#define SMEM_BYTES (BSZ * KDIM * 4)      // 131072

// Split-K partial sums: [SPLITK][BSZ][NDIM]
__device__ float g_partial[SPLITK * BSZ * NDIM];

// ---- packed f32x2 FMA (Blackwell f32x2 pipe) ----
__device__ __forceinline__ void ffma2(unsigned long long& d,
                                      unsigned long long a,
                                      unsigned long long b) {
    asm("fma.rn.f32x2 %0, %1, %2, %0;" : "+l"(d) : "l"(a), "l"(b));
}
__device__ __forceinline__ float sum2(unsigned long long a) {
    float lo, hi;
    asm("mov.b64 {%0, %1}, %2;" : "=f"(lo), "=f"(hi) : "l"(a));
    return lo + hi;
}
// streaming 128-bit global load as two packed f32x2 words (bypass L1 reuse)
__device__ __forceinline__ void ldg_cs_v2u64(const void* p,
                                             unsigned long long& a,
                                             unsigned long long& b) {
    asm("ld.global.cs.v2.u64 {%0, %1}, [%2];"
        : "=l"(a), "=l"(b) : "l"(p));
}

extern __shared__ float xs[];   // [BSZ][KDIM] staged activations

__global__ __launch_bounds__(THREADS, 1)
void asl_gemv_kernel(const float* __restrict__ x,
                     const float* __restrict__ w) {
    // ---- stage x into shared memory (131 KB), once per CTA ----
    {
        const float4* x4  = reinterpret_cast<const float4*>(x);
        float4*       xs4 = reinterpret_cast<float4*>(xs);
        #pragma unroll 8
        for (int i = threadIdx.x; i < BSZ * KDIM / 4; i += THREADS)
            xs4[i] = x4[i];
    }
    __syncthreads();

    const int lane  = threadIdx.x & 31;
    const int gwarp = blockIdx.x * WARPS_PER_CTA + (threadIdx.x >> 5);
    const ulonglong2* xs2 = reinterpret_cast<const ulonglong2*>(xs);

    for (int task = gwarp; task < NTASKS; task += TOTAL_WARPS) {
        const int bh    = task & 1;            // batch half
        const int kc    = (task >> 1) & 3;     // K-chunk
        const int rg    = task >> 3;           // row group
        const int n0    = rg * RPW;
        const int b0    = bh * BPT;
        const int kbase = kc * KCH;

        const char* wr = reinterpret_cast<const char*>(
            w + (size_t)n0 * KDIM + kbase);
        const ulonglong2* xb = xs2 + (kbase >> 2) +
                               (size_t)b0 * (KDIM / 4);

        unsigned long long acc[RPW][BPT];
        #pragma unroll
        for (int r = 0; r < RPW; r++)
            #pragma unroll
            for (int b = 0; b < BPT; b++)
                acc[r][b] = 0ULL;

        #pragma unroll 1
        for (int it = 0; it < KITERS; it++) {
            const int koff = (it * 32 + lane) * 16;   // byte offset in chunk

            unsigned long long wv[RPW][2];
            #pragma unroll
            for (int r = 0; r < RPW; r++)
                ldg_cs_v2u64(wr + (size_t)r * KDIM * 4 + koff,
                             wv[r][0], wv[r][1]);

            const int xoff = it * 32 + lane;          // 16B-unit offset
            #pragma unroll
            for (int b = 0; b < BPT; b++) {
                ulonglong2 xv = xb[b * (KDIM / 4) + xoff];
                #pragma unroll
                for (int r = 0; r < RPW; r++) {
                    ffma2(acc[r][b], wv[r][0], xv.x);
                    ffma2(acc[r][b], wv[r][1], xv.y);
                }
            }
        }

        // ---- warp reduction: collapse f32x2 -> f32, 5-step shfl_down ----
        float vals[RPW][BPT];
        #pragma unroll
        for (int r = 0; r < RPW; r++) {
            #pragma unroll
            for (int b = 0; b < BPT; b++) {
                float s = sum2(acc[r][b]);
                s += __shfl_down_sync(0xFFFFFFFFu, s, 16);
                s += __shfl_down_sync(0xFFFFFFFFu, s, 8);
                s += __shfl_down_sync(0xFFFFFFFFu, s, 4);
                s += __shfl_down_sync(0xFFFFFFFFu, s, 2);
                s += __shfl_down_sync(0xFFFFFFFFu, s, 1);
                vals[r][b] = s;
            }
        }

        if (lane == 0) {
            #pragma unroll
            for (int b = 0; b < BPT; b++) {
                float* dst = g_partial +
                    ((size_t)kc * BSZ + b0 + b) * NDIM + n0;
                float4 o0, o1;
                o0.x = vals[0][b]; o0.y = vals[1][b];
                o0.z = vals[2][b]; o0.w = vals[3][b];
                o1.x = vals[4][b]; o1.y = vals[5][b];
                o1.z = vals[6][b]; o1.w = vals[7][b];
                *reinterpret_cast<float4*>(dst)     = o0;
                *reinterpret_cast<float4*>(dst + 4) = o1;
            }
        }
    }
}

// out[b*NDIM+n] = sum over SPLITK partials (fully coalesced float4)
__global__ void asl_combine_kernel(float* __restrict__ out) {
    const int i = blockIdx.x * blockDim.x + threadIdx.x;   // float4 index
    const int total4 = BSZ * NDIM / 4;                     // 22016
    if (i < total4) {
        const float4* p4 = reinterpret_cast<const float4*>(g_partial);
        float4 a0 = p4[i];
        float4 a1 = p4[i +     total4];
        float4 a2 = p4[i + 2 * total4];
        float4 a3 = p4[i + 3 * total4];
        float4 o;
        o.x = (a0.x + a1.x) + (a2.x + a3.x);
        o.y = (a0.y + a1.y) + (a2.y + a3.y);
        o.z = (a0.z + a1.z) + (a2.z + a3.z);
        o.w = (a0.w + a1.w) + (a2.w + a3.w);
        reinterpret_cast<float4*>(out)[i] = o;
    }
}

extern "C" void kernel_launch(void* const* d_in, const int* in_sizes, int n_in,
                              void* d_out, int out_size) {
    const float* x = (const float*)d_in[0];
    const float* w = (const float*)d_in[1];
    if (n_in >= 2 && in_sizes[0] == NDIM * KDIM) {   // defensive order fix
        const float* t = x; x = w; w = t;
    }
    float* out = (float*)d_out;

    cudaFuncSetAttribute(asl_gemv_kernel,
                         cudaFuncAttributeMaxDynamicSharedMemorySize,
                         SMEM_BYTES);

    asl_gemv_kernel<<<NCTAS, THREADS, SMEM_BYTES>>>(x, w);

    const int total4 = BSZ * NDIM / 4;
    asl_combine_kernel<<<(total4 + 255) / 256, 256>>>(out);
}

// round 8
// speedup vs baseline: 1.6532x; 1.2056x over previous
#include <cuda_runtime.h>
#include <cstdint>

// Problem constants
#define BSZ     8
#define KDIM    4096
#define NDIM    11008
#define RPW     4                        // rows per warp task
#define SPLITK  4
#define KCH     (KDIM / SPLITK)          // 1024 floats per K-chunk
#define KITERS  (KCH / 128)              // 8 iterations (128 floats/row/iter)
#define WARPS_PER_CTA 16
#define THREADS (WARPS_PER_CTA * 32)     // 512
#define NCTAS   148
#define TOTAL_WARPS (NCTAS * WARPS_PER_CTA)   // 2368
#define NROWGROUPS (NDIM / RPW)               // 2752
#define NTASKS  (NROWGROUPS * SPLITK)         // 11008
#define SMEM_BYTES (BSZ * KDIM * 4)           // 131072

// Split-K partial sums: [SPLITK][BSZ][NDIM]
__device__ float g_partial[SPLITK * BSZ * NDIM];

// ---- packed f32x2 FMA (Blackwell f32x2 pipe) ----
__device__ __forceinline__ void ffma2(unsigned long long& d,
                                      unsigned long long a,
                                      unsigned long long b) {
    asm("fma.rn.f32x2 %0, %1, %2, %0;" : "+l"(d) : "l"(a), "l"(b));
}
__device__ __forceinline__ float sum2(unsigned long long a) {
    float lo, hi;
    asm("mov.b64 {%0, %1}, %2;" : "=f"(lo), "=f"(hi) : "l"(a));
    return lo + hi;
}
// streaming 128-bit global load as two packed f32x2 words (bypass L1 reuse)
__device__ __forceinline__ void ldg_cs_v2u64(const void* p,
                                             unsigned long long& a,
                                             unsigned long long& b) {
    asm("ld.global.cs.v2.u64 {%0, %1}, [%2];"
        : "=l"(a), "=l"(b) : "l"(p));
}

extern __shared__ float xs[];   // [BSZ][KDIM] staged activations

__global__ __launch_bounds__(THREADS, 1)
void asl_gemv_kernel(const float* __restrict__ x,
                     const float* __restrict__ w) {
    // ---- stage x into shared memory (131 KB), once per CTA ----
    {
        const float4* x4  = reinterpret_cast<const float4*>(x);
        float4*       xs4 = reinterpret_cast<float4*>(xs);
        #pragma unroll 8
        for (int i = threadIdx.x; i < BSZ * KDIM / 4; i += THREADS)
            xs4[i] = x4[i];
    }
    __syncthreads();

    const int lane  = threadIdx.x & 31;
    const int gwarp = blockIdx.x * WARPS_PER_CTA + (threadIdx.x >> 5);
    const ulonglong2* xs2 = reinterpret_cast<const ulonglong2*>(xs);

    for (int task = gwarp; task < NTASKS; task += TOTAL_WARPS) {
        const int rg    = task >> 2;          // row group
        const int kc    = task & 3;           // K-chunk
        const int n0    = rg * RPW;
        const int kbase = kc * KCH;           // float offset into K

        const char* wr = reinterpret_cast<const char*>(
            w + (size_t)n0 * KDIM + kbase);
        const ulonglong2* xb = xs2 + (kbase >> 2);  // x chunk base (16B units)

        unsigned long long acc[RPW][BSZ];
        #pragma unroll
        for (int r = 0; r < RPW; r++)
            #pragma unroll
            for (int b = 0; b < BSZ; b++)
                acc[r][b] = 0ULL;

        #pragma unroll 2
        for (int it = 0; it < KITERS; it++) {
            const int koff = (it * 32 + lane) * 16;   // byte offset in chunk

            unsigned long long w0l, w0h, w1l, w1h, w2l, w2h, w3l, w3h;
            ldg_cs_v2u64(wr +                 koff, w0l, w0h);
            ldg_cs_v2u64(wr +     KDIM * 4 +  koff, w1l, w1h);
            ldg_cs_v2u64(wr + 2 * KDIM * 4 +  koff, w2l, w2h);
            ldg_cs_v2u64(wr + 3 * KDIM * 4 +  koff, w3l, w3h);

            const int xoff = it * 32 + lane;          // 16B-unit offset
            #pragma unroll
            for (int b = 0; b < BSZ; b++) {
                ulonglong2 xv = xb[b * (KDIM / 4) + xoff];
                ffma2(acc[0][b], w0l, xv.x); ffma2(acc[0][b], w0h, xv.y);
                ffma2(acc[1][b], w1l, xv.x); ffma2(acc[1][b], w1h, xv.y);
                ffma2(acc[2][b], w2l, xv.x); ffma2(acc[2][b], w2h, xv.y);
                ffma2(acc[3][b], w3l, xv.x); ffma2(acc[3][b], w3h, xv.y);
            }
        }

        // ---- butterfly epilogue: 32 partials across 32 lanes in 31 SHFL ----
        // v[l] corresponds to (r = l & 3, b = l >> 2); after 5 xor-rounds,
        // lane l holds the full warp sum of v[l].
        float v[32];
        #pragma unroll
        for (int b = 0; b < BSZ; b++)
            #pragma unroll
            for (int r = 0; r < RPW; r++)
                v[b * RPW + r] = sum2(acc[r][b]);

        #pragma unroll
        for (int s = 16; s >= 1; s >>= 1) {
            const bool hi = (lane & s) != 0;
            #pragma unroll
            for (int j = 0; j < s; j++) {
                float mine  = hi ? v[j + s] : v[j];
                float sent  = hi ? v[j]     : v[j + s];
                float other = __shfl_xor_sync(0xFFFFFFFFu, sent, s);
                v[j] = mine + other;
            }
        }

        // lane l -> g_partial[kc][b = l>>2][n0 + (l&3)]
        g_partial[((size_t)kc * BSZ + (lane >> 2)) * NDIM + n0 + (lane & 3)]
            = v[0];
    }
}

// out[b*NDIM+n] = sum over SPLITK partials (fully coalesced float4)
__global__ void asl_combine_kernel(float* __restrict__ out) {
    const int i = blockIdx.x * blockDim.x + threadIdx.x;   // float4 index
    const int total4 = BSZ * NDIM / 4;                     // 22016
    if (i < total4) {
        const float4* p4 = reinterpret_cast<const float4*>(g_partial);
        float4 a0 = p4[i];
        float4 a1 = p4[i +     total4];
        float4 a2 = p4[i + 2 * total4];
        float4 a3 = p4[i + 3 * total4];
        float4 o;
        o.x = (a0.x + a1.x) + (a2.x + a3.x);
        o.y = (a0.y + a1.y) + (a2.y + a3.y);
        o.z = (a0.z + a1.z) + (a2.z + a3.z);
        o.w = (a0.w + a1.w) + (a2.w + a3.w);
        reinterpret_cast<float4*>(out)[i] = o;
    }
}

extern "C" void kernel_launch(void* const* d_in, const int* in_sizes, int n_in,
                              void* d_out, int out_size) {
    const float* x = (const float*)d_in[0];
    const float* w = (const float*)d_in[1];
    if (n_in >= 2 && in_sizes[0] == NDIM * KDIM) {   // defensive order fix
        const float* t = x; x = w; w = t;
    }
    float* out = (float*)d_out;

    cudaFuncSetAttribute(asl_gemv_kernel,
                         cudaFuncAttributeMaxDynamicSharedMemorySize,
                         SMEM_BYTES);

    asl_gemv_kernel<<<NCTAS, THREADS, SMEM_BYTES>>>(x, w);

    const int total4 = BSZ * NDIM / 4;   // 22016
    asl_combine_kernel<<<(total4 + 127) / 128, 128>>>(out);
}